// round 1
// baseline (speedup 1.0000x reference)
#include <cuda_runtime.h>
#include <cstdint>
#include <math.h>

#define NN 8
#define BB 64
#define TT 256
#define INP 64
#define HH 512
#define GG 2048   /* 4*H */
#define MM 512
#define OO 7

// ---------------- scratch (static device globals; no allocation) ----------------
__device__ float g_z[(size_t)BB * TT * HH];                 // [B][T][H]      32 MB
__device__ float g_xg0[(size_t)TT * NN * BB * GG];          // [T][N][B][4H]   1 GiB
__device__ float g_h0[2][NN * BB * HH];
__device__ float g_h1[2][NN * BB * HH];
__device__ float g_c0[NN * BB * HH];
__device__ float g_c1[NN * BB * HH];
__device__ float g_y[(size_t)NN * BB * TT * HH];            // [N][B][T][H]  256 MB
__device__ float g_hid[(size_t)NN * BB * TT * MM];          // [N][BT][M]    256 MB
__device__ unsigned g_barc;
__device__ unsigned g_barg;

__device__ __forceinline__ float sigf(float x) { return 1.0f / (1.0f + expf(-x)); }

// ---------------- init: zero states + barrier counters ----------------
__global__ void k_init() {
    int i = blockIdx.x * blockDim.x + threadIdx.x;
    int stride = gridDim.x * blockDim.x;
    for (int j = i; j < NN * BB * HH; j += stride) {
        g_h0[0][j] = 0.0f;
        g_h1[0][j] = 0.0f;
        g_c0[j] = 0.0f;
        g_c1[j] = 0.0f;
    }
    if (i == 0) { g_barc = 0u; g_barg = 0u; }
}

// ---------------- input layer: z = leaky(x @ Win^T + bin)*10 ----------------
// tile 64 rows x 128 cols, K=64
__global__ void __launch_bounds__(256) k_input(const float* __restrict__ x,
                                               const float* __restrict__ Win,
                                               const float* __restrict__ bin_) {
    __shared__ __align__(16) float As[16][68];
    __shared__ __align__(16) float Bs[16][132];
    int tid = threadIdx.x;
    int tc = tid & 15, tr = tid >> 4;
    int row0 = blockIdx.x * 64;      // flat (b*T+t)
    int c0 = blockIdx.y * 128;       // h
    float acc[4][8];
#pragma unroll
    for (int i = 0; i < 4; i++)
#pragma unroll
        for (int j = 0; j < 8; j++) acc[i][j] = 0.0f;

    for (int k0 = 0; k0 < INP; k0 += 16) {
        {
            int r = tid >> 2, kq = (tid & 3) * 4;
            float4 v = *(const float4*)(x + (size_t)(row0 + r) * INP + k0 + kq);
            As[kq + 0][r] = v.x; As[kq + 1][r] = v.y; As[kq + 2][r] = v.z; As[kq + 3][r] = v.w;
        }
        {
            int c = tid >> 1, kh = (tid & 1) * 8;
            const float* p = Win + (size_t)(c0 + c) * INP + k0 + kh;
            float4 v0 = *(const float4*)p;
            float4 v1 = *(const float4*)(p + 4);
            Bs[kh + 0][c] = v0.x; Bs[kh + 1][c] = v0.y; Bs[kh + 2][c] = v0.z; Bs[kh + 3][c] = v0.w;
            Bs[kh + 4][c] = v1.x; Bs[kh + 5][c] = v1.y; Bs[kh + 6][c] = v1.z; Bs[kh + 7][c] = v1.w;
        }
        __syncthreads();
#pragma unroll
        for (int kk = 0; kk < 16; kk++) {
            float4 a = *(const float4*)&As[kk][tr * 4];
            float4 b0 = *(const float4*)&Bs[kk][tc * 8];
            float4 b1 = *(const float4*)&Bs[kk][tc * 8 + 4];
            float av[4] = {a.x, a.y, a.z, a.w};
            float bv[8] = {b0.x, b0.y, b0.z, b0.w, b1.x, b1.y, b1.z, b1.w};
#pragma unroll
            for (int i = 0; i < 4; i++)
#pragma unroll
                for (int j = 0; j < 8; j++) acc[i][j] = fmaf(av[i], bv[j], acc[i][j]);
        }
        __syncthreads();
    }
#pragma unroll
    for (int i = 0; i < 4; i++) {
        int row = row0 + tr * 4 + i;
#pragma unroll
        for (int j = 0; j < 8; j++) {
            int h = c0 + tc * 8 + j;
            float v = acc[i][j] + bin_[h];
            v = (v > 0.0f ? v : 0.2f * v) * 10.0f;
            g_z[(size_t)row * HH + h] = v;
        }
    }
}

// ---------------- xg0 precompute: xg0[t][n][b][gc] = z[b,t,:] @ W_ih0[n,gc,:] + b_ih0 + b_hh0 ----------------
// tile: 64 t-rows (fixed b) x 128 gate-cols, K=512
__global__ void __launch_bounds__(256) k_xg0(const float* __restrict__ W_ih0,
                                             const float* __restrict__ b_ih0,
                                             const float* __restrict__ b_hh0) {
    __shared__ __align__(16) float As[16][68];
    __shared__ __align__(16) float Bs[16][132];
    int tid = threadIdx.x;
    int tc = tid & 15, tr = tid >> 4;
    int rt = blockIdx.x;
    int b = rt >> 2;
    int t0 = (rt & 3) * 64;
    int gc0 = blockIdx.y * 128;
    int n = blockIdx.z;
    const float* Abase = g_z + ((size_t)b * TT + t0) * HH;
    const float* Bbase = W_ih0 + (size_t)n * GG * HH + (size_t)gc0 * HH;
    float acc[4][8];
#pragma unroll
    for (int i = 0; i < 4; i++)
#pragma unroll
        for (int j = 0; j < 8; j++) acc[i][j] = 0.0f;

    for (int k0 = 0; k0 < HH; k0 += 16) {
        {
            int r = tid >> 2, kq = (tid & 3) * 4;
            float4 v = *(const float4*)(Abase + (size_t)r * HH + k0 + kq);
            As[kq + 0][r] = v.x; As[kq + 1][r] = v.y; As[kq + 2][r] = v.z; As[kq + 3][r] = v.w;
        }
        {
            int c = tid >> 1, kh = (tid & 1) * 8;
            const float* p = Bbase + (size_t)c * HH + k0 + kh;
            float4 v0 = *(const float4*)p;
            float4 v1 = *(const float4*)(p + 4);
            Bs[kh + 0][c] = v0.x; Bs[kh + 1][c] = v0.y; Bs[kh + 2][c] = v0.z; Bs[kh + 3][c] = v0.w;
            Bs[kh + 4][c] = v1.x; Bs[kh + 5][c] = v1.y; Bs[kh + 6][c] = v1.z; Bs[kh + 7][c] = v1.w;
        }
        __syncthreads();
#pragma unroll
        for (int kk = 0; kk < 16; kk++) {
            float4 a = *(const float4*)&As[kk][tr * 4];
            float4 b0 = *(const float4*)&Bs[kk][tc * 8];
            float4 b1 = *(const float4*)&Bs[kk][tc * 8 + 4];
            float av[4] = {a.x, a.y, a.z, a.w};
            float bv[8] = {b0.x, b0.y, b0.z, b0.w, b1.x, b1.y, b1.z, b1.w};
#pragma unroll
            for (int i = 0; i < 4; i++)
#pragma unroll
                for (int j = 0; j < 8; j++) acc[i][j] = fmaf(av[i], bv[j], acc[i][j]);
        }
        __syncthreads();
    }
#pragma unroll
    for (int i = 0; i < 4; i++) {
        int t = t0 + tr * 4 + i;
        size_t ob = ((size_t)t * NN + n) * (BB * GG) + (size_t)b * GG;
#pragma unroll
        for (int j = 0; j < 8; j++) {
            int gc = gc0 + tc * 8 + j;
            g_xg0[ob + gc] = acc[i][j] + b_ih0[(size_t)n * GG + gc] + b_hh0[(size_t)n * GG + gc];
        }
    }
}

// ---------------- grid barrier (all blocks co-resident by construction) ----------------
__device__ __forceinline__ void grid_bar(unsigned nb) {
    __syncthreads();
    if (threadIdx.x == 0) {
        __threadfence();
        unsigned gen = atomicAdd(&g_barg, 0u);
        unsigned t = atomicAdd(&g_barc, 1u);
        if (t == nb - 1u) {
            atomicExch(&g_barc, 0u);
            __threadfence();
            atomicAdd(&g_barg, 1u);
        } else {
            while (atomicAdd(&g_barg, 0u) == gen) { __nanosleep(64); }
        }
        __threadfence();
    }
    __syncthreads();
}

// recurrent GEMM fragment: rows = 64 batch, cols = 64 = 16 hidden x 4 gates, K = 512
// col c -> weight row = (c&3)*512 + hh0 + (c>>2); thread tc owns hidden hh0+tc, all 4 gates.
__device__ __forceinline__ void rec_gemm(const float* __restrict__ Abase,
                                         const float* __restrict__ Wbase,
                                         int hh0, float (&acc)[4][4],
                                         float (*As)[68], float (*Bs)[68],
                                         int tid, int tr, int tc) {
    for (int k0 = 0; k0 < HH; k0 += 16) {
        int r = tid >> 2, kq = (tid & 3) * 4;
        float4 av = *(const float4*)(Abase + (size_t)r * HH + k0 + kq);
        As[kq + 0][r] = av.x; As[kq + 1][r] = av.y; As[kq + 2][r] = av.z; As[kq + 3][r] = av.w;
        int cc = r;  // same mapping reused for B cols
        int wrow = (cc & 3) * HH + hh0 + (cc >> 2);
        float4 bv = *(const float4*)(Wbase + (size_t)wrow * HH + k0 + kq);
        Bs[kq + 0][cc] = bv.x; Bs[kq + 1][cc] = bv.y; Bs[kq + 2][cc] = bv.z; Bs[kq + 3][cc] = bv.w;
        __syncthreads();
#pragma unroll
        for (int kk = 0; kk < 16; kk++) {
            float4 a = *(const float4*)&As[kk][tr * 4];
            float4 b = *(const float4*)&Bs[kk][tc * 4];
            float av2[4] = {a.x, a.y, a.z, a.w};
            float bv2[4] = {b.x, b.y, b.z, b.w};
#pragma unroll
            for (int i = 0; i < 4; i++)
#pragma unroll
                for (int j = 0; j < 4; j++) acc[i][j] = fmaf(av2[i], bv2[j], acc[i][j]);
        }
        __syncthreads();
    }
}

// ---------------- persistent sequential LSTM (both layers), 256 blocks ----------------
__global__ void __launch_bounds__(256) k_rec(const float* __restrict__ W_hh0,
                                             const float* __restrict__ W_ih1,
                                             const float* __restrict__ W_hh1,
                                             const float* __restrict__ b_ih1,
                                             const float* __restrict__ b_hh1) {
    __shared__ __align__(16) float As[16][68];
    __shared__ __align__(16) float Bs[16][68];
    int tid = threadIdx.x;
    int tc = tid & 15, tr = tid >> 4;
    int n = blockIdx.x >> 5;      // 8 generators
    int ct = blockIdx.x & 31;     // 32 column tiles of 16 hidden units
    int hh0 = ct * 16;
    unsigned nb = gridDim.x;
    const float* Whh0n = W_hh0 + (size_t)n * GG * HH;
    const float* Wih1n = W_ih1 + (size_t)n * GG * HH;
    const float* Whh1n = W_hh1 + (size_t)n * GG * HH;
    size_t st = (size_t)n * BB * HH;
    int h = hh0 + tc;

    float bias1[4];
#pragma unroll
    for (int g = 0; g < 4; g++)
        bias1[g] = b_ih1[(size_t)n * GG + g * HH + h] + b_hh1[(size_t)n * GG + g * HH + h];

    for (int t = 0; t < TT; t++) {
        int p = t & 1;
        // ---- layer 0 ----
        float acc[4][4];
#pragma unroll
        for (int i = 0; i < 4; i++)
#pragma unroll
            for (int j = 0; j < 4; j++) acc[i][j] = 0.0f;
        rec_gemm(g_h0[p] + st, Whh0n, hh0, acc, As, Bs, tid, tr, tc);
        {
            const float* xg = g_xg0 + ((size_t)t * NN + n) * ((size_t)BB * GG);
#pragma unroll
            for (int i = 0; i < 4; i++) {
                int b = tr * 4 + i;
                const float* xgb = xg + (size_t)b * GG;
                float pi = acc[i][0] + xgb[h];
                float pf = acc[i][1] + xgb[HH + h];
                float pg = acc[i][2] + xgb[2 * HH + h];
                float po = acc[i][3] + xgb[3 * HH + h];
                size_t idx = st + (size_t)b * HH + h;
                float co = g_c0[idx];
                float cn = sigf(pf) * co + sigf(pi) * tanhf(pg);
                float hn = sigf(po) * tanhf(cn);
                g_c0[idx] = cn;
                g_h0[p ^ 1][idx] = hn;
            }
        }
        grid_bar(nb);
        // ---- layer 1 ----
#pragma unroll
        for (int i = 0; i < 4; i++)
#pragma unroll
            for (int j = 0; j < 4; j++) acc[i][j] = 0.0f;
        rec_gemm(g_h0[p ^ 1] + st, Wih1n, hh0, acc, As, Bs, tid, tr, tc);
        rec_gemm(g_h1[p] + st, Whh1n, hh0, acc, As, Bs, tid, tr, tc);
        {
#pragma unroll
            for (int i = 0; i < 4; i++) {
                int b = tr * 4 + i;
                float pi = acc[i][0] + bias1[0];
                float pf = acc[i][1] + bias1[1];
                float pg = acc[i][2] + bias1[2];
                float po = acc[i][3] + bias1[3];
                size_t idx = st + (size_t)b * HH + h;
                float co = g_c1[idx];
                float cn = sigf(pf) * co + sigf(pi) * tanhf(pg);
                float hn = sigf(po) * tanhf(cn);
                g_c1[idx] = cn;
                g_h1[p ^ 1][idx] = hn;
                g_y[(((size_t)n * BB + b) * TT + t) * HH + h] = hn;
            }
        }
        grid_bar(nb);
    }
}

// ---------------- heads stage 1: hid = leaky(y @ Wh1^T + bh1) ----------------
__global__ void __launch_bounds__(256) k_heads1(const float* __restrict__ Wh1,
                                                const float* __restrict__ bh1) {
    __shared__ __align__(16) float As[16][68];
    __shared__ __align__(16) float Bs[16][132];
    int tid = threadIdx.x;
    int tc = tid & 15, tr = tid >> 4;
    int row0 = blockIdx.x * 64;       // bt rows
    int m0 = blockIdx.y * 128;
    int n = blockIdx.z;
    const float* Abase = g_y + ((size_t)n * BB * TT + row0) * HH;
    const float* Bbase = Wh1 + (size_t)n * MM * HH + (size_t)m0 * HH;
    float acc[4][8];
#pragma unroll
    for (int i = 0; i < 4; i++)
#pragma unroll
        for (int j = 0; j < 8; j++) acc[i][j] = 0.0f;

    for (int k0 = 0; k0 < HH; k0 += 16) {
        {
            int r = tid >> 2, kq = (tid & 3) * 4;
            float4 v = *(const float4*)(Abase + (size_t)r * HH + k0 + kq);
            As[kq + 0][r] = v.x; As[kq + 1][r] = v.y; As[kq + 2][r] = v.z; As[kq + 3][r] = v.w;
        }
        {
            int c = tid >> 1, kh = (tid & 1) * 8;
            const float* p = Bbase + (size_t)c * HH + k0 + kh;
            float4 v0 = *(const float4*)p;
            float4 v1 = *(const float4*)(p + 4);
            Bs[kh + 0][c] = v0.x; Bs[kh + 1][c] = v0.y; Bs[kh + 2][c] = v0.z; Bs[kh + 3][c] = v0.w;
            Bs[kh + 4][c] = v1.x; Bs[kh + 5][c] = v1.y; Bs[kh + 6][c] = v1.z; Bs[kh + 7][c] = v1.w;
        }
        __syncthreads();
#pragma unroll
        for (int kk = 0; kk < 16; kk++) {
            float4 a = *(const float4*)&As[kk][tr * 4];
            float4 b0 = *(const float4*)&Bs[kk][tc * 8];
            float4 b1 = *(const float4*)&Bs[kk][tc * 8 + 4];
            float av[4] = {a.x, a.y, a.z, a.w};
            float bv[8] = {b0.x, b0.y, b0.z, b0.w, b1.x, b1.y, b1.z, b1.w};
#pragma unroll
            for (int i = 0; i < 4; i++)
#pragma unroll
                for (int j = 0; j < 8; j++) acc[i][j] = fmaf(av[i], bv[j], acc[i][j]);
        }
        __syncthreads();
    }
#pragma unroll
    for (int i = 0; i < 4; i++) {
        int row = row0 + tr * 4 + i;
#pragma unroll
        for (int j = 0; j < 8; j++) {
            int m = m0 + tc * 8 + j;
            float v = acc[i][j] + bh1[(size_t)n * MM + m];
            v = (v > 0.0f ? v : 0.2f * v);
            g_hid[((size_t)n * BB * TT + row) * MM + m] = v;
        }
    }
}

// ---------------- heads stage 2: out = hid @ Wh2^T + bh2 (warp per row) ----------------
__global__ void __launch_bounds__(256) k_heads2(const float* __restrict__ Wh2,
                                                const float* __restrict__ bh2,
                                                float* __restrict__ out) {
    int gw = (blockIdx.x * blockDim.x + threadIdx.x) >> 5;
    int lane = threadIdx.x & 31;
    if (gw >= NN * BB * TT) return;
    int n = gw >> 14;  // / 16384
    const float* hrow = g_hid + (size_t)gw * MM;
    float hv[16];
#pragma unroll
    for (int q = 0; q < 4; q++) {
        float4 v = *(const float4*)(hrow + lane * 16 + q * 4);
        hv[q * 4 + 0] = v.x; hv[q * 4 + 1] = v.y; hv[q * 4 + 2] = v.z; hv[q * 4 + 3] = v.w;
    }
    const float* W = Wh2 + (size_t)n * OO * MM;
#pragma unroll
    for (int o = 0; o < OO; o++) {
        const float4* w4 = (const float4*)(W + (size_t)o * MM + lane * 16);
        float s = 0.0f;
#pragma unroll
        for (int q = 0; q < 4; q++) {
            float4 w = w4[q];
            s += hv[q * 4 + 0] * w.x + hv[q * 4 + 1] * w.y + hv[q * 4 + 2] * w.z + hv[q * 4 + 3] * w.w;
        }
#pragma unroll
        for (int off = 16; off > 0; off >>= 1) s += __shfl_xor_sync(0xFFFFFFFFu, s, off);
        if (lane == 0) out[(size_t)gw * OO + o] = s + bh2[(size_t)n * OO + o];
    }
}

// ---------------- launch ----------------
extern "C" void kernel_launch(void* const* d_in, const int* in_sizes, int n_in,
                              void* d_out, int out_size) {
    const float* x     = (const float*)d_in[0];
    const float* Win   = (const float*)d_in[1];
    const float* bin_  = (const float*)d_in[2];
    const float* W_ih0 = (const float*)d_in[3];
    const float* W_hh0 = (const float*)d_in[4];
    const float* b_ih0 = (const float*)d_in[5];
    const float* b_hh0 = (const float*)d_in[6];
    const float* W_ih1 = (const float*)d_in[7];
    const float* W_hh1 = (const float*)d_in[8];
    const float* b_ih1 = (const float*)d_in[9];
    const float* b_hh1 = (const float*)d_in[10];
    const float* Wh1   = (const float*)d_in[11];
    const float* bh1   = (const float*)d_in[12];
    const float* Wh2   = (const float*)d_in[13];
    const float* bh2   = (const float*)d_in[14];
    float* out = (float*)d_out;

    k_init<<<256, 256>>>();
    k_input<<<dim3(BB * TT / 64, HH / 128), 256>>>(x, Win, bin_);
    k_xg0<<<dim3(BB * 4, GG / 128, NN), 256>>>(W_ih0, b_ih0, b_hh0);
    k_rec<<<256, 256>>>(W_hh0, W_ih1, W_hh1, b_ih1, b_hh1);
    k_heads1<<<dim3(BB * TT / 64, MM / 128, NN), 256>>>(Wh1, bh1);
    k_heads2<<<(NN * BB * TT) / 8, 256>>>(Wh2, bh2, out);
}